// round 9
// baseline (speedup 1.0000x reference)
#include <cuda_runtime.h>
#include <math.h>
#include <stdint.h>

#define BB 8
#define NN 4096
#define CC 96
#define C2 192
#define NP 1024
#define NSAMP 16
#define FULLMASK 0xffffffffu
#define KC 32

// ---- packed f32x2 helpers (exact per-lane IEEE RN, sm_103a) ----
#define MUL_F32X2(out, a, b) \
    asm("mul.rn.f32x2 %0, %1, %2;" : "=l"(out) : "l"(a), "l"(b))
#define ADD_F32X2(out, a, b) \
    asm("add.rn.f32x2 %0, %1, %2;" : "=l"(out) : "l"(a), "l"(b))
#define FMA_F32X2(d, a, b) \
    asm("fma.rn.f32x2 %0, %1, %2, %0;" : "+l"(d) : "l"(a), "l"(b))
#define UNPACK_F32X2(lo, hi, in) \
    asm("mov.b64 {%0, %1}, %2;" : "=r"(lo), "=r"(hi) : "l"(in))

__device__ __forceinline__ unsigned long long pack2u(unsigned lo, unsigned hi) {
    unsigned long long r;
    asm("mov.b64 %0, {%1, %2};" : "=l"(r) : "r"(lo), "r"(hi));
    return r;
}
__device__ __forceinline__ unsigned long long pack2f(float lo, float hi) {
    return pack2u(__float_as_uint(lo), __float_as_uint(hi));
}

// ---- acquire/release for cross-block pipelining ----
__device__ __forceinline__ int ld_acquire(const int* p) {
    int v;
    asm volatile("ld.global.acquire.gpu.b32 %0, [%1];" : "=r"(v) : "l"(p) : "memory");
    return v;
}
__device__ __forceinline__ void st_release(int* p, int v) {
    asm volatile("st.global.release.gpu.b32 [%0], %1;" :: "l"(p), "r"(v) : "memory");
}

// ---------------- scratch ----------------
__device__ int   d_samp[BB*NP];
__device__ int   d_nbr[BB*NP*NSAMP];
__device__ float d_Bfeat[BB*NN*C2];    // [b][n][c]
__device__ float d_Afeat[BB*NP*C2];    // [b][g][c]
__device__ float d_Pool[BB*NP*C2];     // [b][g][c]
__device__ int   d_cellStart[BB][1001];
__device__ int   d_cellPts[BB][NN];
// pipelining flags (zero-init; stale values across graph replays are benign
// because every guarded buffer is rewritten with byte-identical contents)
__device__ __align__(128) int d_progress[BB*32];
__device__ __align__(128) int d_gridready[BB*32];

__device__ __forceinline__ int cellof(float x, float y, float z) {
    int ix = min(9, max(0, (int)(x * 9.99f)));
    int iy = min(9, max(0, (int)(y * 9.99f)));
    int iz = min(9, max(0, (int)(z * 9.99f)));
    return (ix * 10 + iy) * 10 + iz;
}

__device__ __forceinline__ int spread3(int b) {
    return (b & 1) | ((b & 2) << 2) | ((b & 4) << 4);
}

// ---------------- FPS body: 512 threads, 8 pts/thread, warp-bbox pruning ----------------
// Exactness: a warp skips ONLY when lb2(warp bbox)*0.999 >= warp_max(mind).
// Then every distance satisfies fl(d_i) >= mind_i (fp margin >100x rounding),
// so minds are provably unchanged. Tie keys = origidx<<12|pos => min original
// index among ties (jnp.argmax first-occurrence order).
__device__ __forceinline__ void fps_body(char* smraw, const float* __restrict__ p,
                                         float* __restrict__ newp, int b) {
    float* ssx = (float*)smraw;
    float* ssy = ssx + NN;
    float* ssz = ssy + NN;
    unsigned short* sorig = (unsigned short*)(ssz + NN);
    int* scnt  = (int*)(sorig + NN);
    int* scnt2 = scnt + 512;
    unsigned short* scell = (unsigned short*)(scnt2 + 512);
    unsigned* sred = (unsigned*)(scell + NN);

    int tid = threadIdx.x, lane = tid & 31, warp = tid >> 5;
    const float* pb = p + (size_t)b * NN * 3;

    // ---- counting sort into 512 Morton cells (block-private; output-neutral) ----
    for (int i = tid; i < 512; i += 512) scnt[i] = 0;
    __syncthreads();
    for (int i = tid; i < NN; i += 512) {
        float xx = pb[3*i], yy = pb[3*i+1], zz = pb[3*i+2];
        int ix = min(7, max(0, (int)(xx * 8.0f)));
        int iy = min(7, max(0, (int)(yy * 8.0f)));
        int iz = min(7, max(0, (int)(zz * 8.0f)));
        int cell = (spread3(ix) << 2) | (spread3(iy) << 1) | spread3(iz);
        scell[i] = (unsigned short)cell;
        atomicAdd(&scnt[cell], 1);
    }
    __syncthreads();
    {
        int* src = scnt; int* dst = scnt2;
        for (int off = 1; off < 512; off <<= 1) {
            for (int i = tid; i < 512; i += 512)
                dst[i] = src[i] + ((i >= off) ? src[i - off] : 0);
            __syncthreads();
            int* t = src; src = dst; dst = t;
        }
        for (int i = tid; i < 512; i += 512)
            dst[i] = (i == 0) ? 0 : src[i-1];
        __syncthreads();
        for (int i = tid; i < NN; i += 512) {
            int cell = scell[i];
            int pos = atomicAdd(&dst[cell], 1);
            ssx[pos] = pb[3*i];
            ssy[pos] = pb[3*i+1];
            ssz[pos] = pb[3*i+2];
            sorig[pos] = (unsigned short)i;
        }
    }
    __syncthreads();

    const int base = tid * 8;
    float vx[8], vy[8], vz[8];
    #pragma unroll
    for (int i = 0; i < 8; i++) {
        vx[i] = ssx[base + i];
        vy[i] = ssy[base + i];
        vz[i] = ssz[base + i];
    }
    unsigned long long pxp[4], pyp[4], pzp[4];
    #pragma unroll
    for (int j = 0; j < 4; j++) {
        pxp[j] = pack2f(vx[2*j], vx[2*j+1]);
        pyp[j] = pack2f(vy[2*j], vy[2*j+1]);
        pzp[j] = pack2f(vz[2*j], vz[2*j+1]);
    }
    float bxlo = vx[0], bxhi = vx[0], bylo = vy[0], byhi = vy[0], bzlo = vz[0], bzhi = vz[0];
    #pragma unroll
    for (int i = 1; i < 8; i++) {
        bxlo = fminf(bxlo, vx[i]); bxhi = fmaxf(bxhi, vx[i]);
        bylo = fminf(bylo, vy[i]); byhi = fmaxf(byhi, vy[i]);
        bzlo = fminf(bzlo, vz[i]); bzhi = fmaxf(bzhi, vz[i]);
    }
    #pragma unroll
    for (int o = 16; o; o >>= 1) {
        bxlo = fminf(bxlo, __shfl_xor_sync(FULLMASK, bxlo, o));
        bxhi = fmaxf(bxhi, __shfl_xor_sync(FULLMASK, bxhi, o));
        bylo = fminf(bylo, __shfl_xor_sync(FULLMASK, bylo, o));
        byhi = fmaxf(byhi, __shfl_xor_sync(FULLMASK, byhi, o));
        bzlo = fminf(bzlo, __shfl_xor_sync(FULLMASK, bzlo, o));
        bzhi = fmaxf(bzhi, __shfl_xor_sync(FULLMASK, bzhi, o));
    }
    unsigned opack[8];
    #pragma unroll
    for (int i = 0; i < 8; i++)
        opack[i] = ((unsigned)sorig[base + i] << 12) | (unsigned)(base + i);

    float mind[8];
    #pragma unroll
    for (int i = 0; i < 8; i++) mind[i] = 1e10f;
    float vmaxf = 1e10f;
    unsigned apack = opack[0];
    unsigned wm = __float_as_uint(1e10f);

    float lx = pb[0], ly = pb[1], lz = pb[2];
    if (tid == 0) {
        d_samp[b*NP + 0] = 0;
        newp[(size_t)(b*NP)*3 + 0] = lx;
        newp[(size_t)(b*NP)*3 + 1] = ly;
        newp[(size_t)(b*NP)*3 + 2] = lz;
        st_release(&d_progress[b*32], 1);
    }

    for (int k = 1; k < NP; k++) {
        float tx = fmaxf(fmaxf(bxlo - lx, lx - bxhi), 0.f);
        float ty = fmaxf(fmaxf(bylo - ly, ly - byhi), 0.f);
        float tz = fmaxf(fmaxf(bzlo - lz, lz - bzhi), 0.f);
        float lb2 = tx*tx + ty*ty + tz*tz;
        if (lb2 * 0.999f < __uint_as_float(wm)) {
            unsigned long long nlx = pack2f(-lx, -lx);
            unsigned long long nly = pack2f(-ly, -ly);
            unsigned long long nlz = pack2f(-lz, -lz);
            #pragma unroll
            for (int j = 0; j < 4; j++) {
                unsigned long long dx, dy, dz, t1, t2, t3, s;
                ADD_F32X2(dx, pxp[j], nlx);
                ADD_F32X2(dy, pyp[j], nly);
                ADD_F32X2(dz, pzp[j], nlz);
                MUL_F32X2(t1, dx, dx);
                MUL_F32X2(t2, dy, dy);
                MUL_F32X2(t3, dz, dz);
                ADD_F32X2(s, t1, t2);
                ADD_F32X2(s, s, t3);
                unsigned lo, hi;
                UNPACK_F32X2(lo, hi, s);
                mind[2*j]   = fminf(mind[2*j],   __uint_as_float(lo));
                mind[2*j+1] = fminf(mind[2*j+1], __uint_as_float(hi));
            }
            float a0 = fmaxf(mind[0], mind[1]), a1 = fmaxf(mind[2], mind[3]);
            float a2 = fmaxf(mind[4], mind[5]), a3 = fmaxf(mind[6], mind[7]);
            float v = fmaxf(fmaxf(a0, a1), fmaxf(a2, a3));
            unsigned ci[8];
            #pragma unroll
            for (int i = 0; i < 8; i++)
                ci[i] = (mind[i] == v) ? opack[i] : 0xffffffffu;
            #pragma unroll
            for (int s2 = 4; s2; s2 >>= 1)
                #pragma unroll
                for (int i = 0; i < 4; i++)
                    if (i < s2) ci[i] = min(ci[i], ci[i + s2]);
            vmaxf = v;
            apack = ci[0];
        }
        unsigned vb = __float_as_uint(vmaxf);
        unsigned m = __reduce_max_sync(FULLMASK, vb);
        unsigned cand = (vb == m) ? apack : 0xffffffffu;
        unsigned l = __reduce_min_sync(FULLMASK, cand);
        wm = m;

        int par = (k & 1) << 4;
        if (lane == 0) { sred[par + warp] = m; sred[32 + par + warp] = l; }
        __syncthreads();
        unsigned v16 = (lane < 16) ? sred[par + lane] : 0u;
        unsigned bm = __reduce_max_sync(FULLMASK, v16);
        unsigned i16 = (lane < 16 && v16 == bm) ? sred[32 + par + lane] : 0xffffffffu;
        unsigned wp = __reduce_min_sync(FULLMASK, i16);

        int spos = (int)(wp & 4095u);
        lx = ssx[spos]; ly = ssy[spos]; lz = ssz[spos];
        if (tid == 0) {
            d_samp[b*NP + k] = (int)(wp >> 12);
            newp[(size_t)(b*NP + k)*3 + 0] = lx;
            newp[(size_t)(b*NP + k)*3 + 1] = ly;
            newp[(size_t)(b*NP + k)*3 + 2] = lz;
            st_release(&d_progress[b*32], k + 1);
        }
    }
}

// ---------------- grid build: histogram+scan (deterministic counts) + bitonic
// sort for cellPts (deterministic permutation => replay rewrites are
// byte-identical, making stale-flag races benign) ----------------
__device__ __forceinline__ void gridbuild_body(char* smraw, const float* __restrict__ p, int b) {
    unsigned* keys = (unsigned*)smraw;          // [4096]
    int* a  = (int*)(keys + NN);                // [1024]
    int* bb = a + 1024;                         // [1024]
    int tid = threadIdx.x;
    const float* pb = p + (size_t)b * NN * 3;

    for (int i = tid; i < 1024; i += 512) a[i] = 0;
    __syncthreads();

    for (int i = tid; i < NN; i += 512) {
        int c = cellof(pb[3*i], pb[3*i+1], pb[3*i+2]);
        keys[i] = (unsigned)c * 4096u + (unsigned)i;
        atomicAdd(&a[c], 1);
    }
    __syncthreads();

    int* src = a; int* dst = bb;
    for (int off = 1; off < 1024; off <<= 1) {
        for (int i = tid; i < 1024; i += 512)
            dst[i] = src[i] + ((i >= off) ? src[i - off] : 0);
        __syncthreads();
        int* t = src; src = dst; dst = t;
    }
    for (int i = tid; i <= 1000; i += 512)
        d_cellStart[b][i] = (i == 0) ? 0 : src[i-1];

    // bitonic sort of keys (ascending) — fully deterministic
    for (unsigned k2 = 2; k2 <= NN; k2 <<= 1) {
        for (unsigned j2 = k2 >> 1; j2 > 0; j2 >>= 1) {
            __syncthreads();
            for (int i = tid; i < NN; i += 512) {
                unsigned ixj = (unsigned)i ^ j2;
                if (ixj > (unsigned)i) {
                    unsigned av = keys[i], cv = keys[ixj];
                    bool up = ((i & k2) == 0);
                    if ((av > cv) == up) { keys[i] = cv; keys[ixj] = av; }
                }
            }
        }
    }
    __syncthreads();
    for (int i = tid; i < NN; i += 512)
        d_cellPts[b][i] = (int)(keys[i] & 4095u);
    __syncthreads();
    if (tid == 0) st_release(&d_gridready[b*32], 1);
}

// ---------------- gemmB body: 512 thr, tile 192x128, thread tile 6x8 ----------------
__device__ __forceinline__ void gemmB_body(char* smraw, const float* __restrict__ x,
                                           const float* __restrict__ Wt,
                                           const float* __restrict__ gt, const float* __restrict__ bt,
                                           const float* __restrict__ mt, const float* __restrict__ vt,
                                           int rb) {
    float (*Ws)[C2]  = (float (*)[C2])smraw;
    float (*Xs)[128] = (float (*)[128])(smraw + KC*C2*4);
    float* ssc = (float*)(smraw + KC*C2*4 + KC*128*4);
    float* ssh = ssc + C2;

    int tid = threadIdx.x;
    int b = rb >> 5, n0 = (rb & 31) * 128;
    if (tid < C2) {
        float st = gt[tid] / sqrtf(vt[tid] + 1e-5f);
        ssc[tid] = st;
        ssh[tid] = bt[tid] - mt[tid]*st;
    }
    int rt = tid >> 4, ct = tid & 15;
    float acc[6][8];
    #pragma unroll
    for (int i = 0; i < 6; i++)
        #pragma unroll
        for (int j = 0; j < 8; j++) acc[i][j] = 0.f;

    for (int kc = 0; kc < CC; kc += KC) {
        if (tid < C2) {
            const float4* wr = (const float4*)(Wt + (size_t)tid*C2 + CC + kc);
            #pragma unroll
            for (int q = 0; q < 8; q++) {
                float4 w = wr[q];
                Ws[q*4+0][tid] = w.x; Ws[q*4+1][tid] = w.y;
                Ws[q*4+2][tid] = w.z; Ws[q*4+3][tid] = w.w;
            }
        }
        #pragma unroll
        for (int e = 0; e < 8; e++) {
            int idx = e*512 + tid;
            int kk = idx >> 7, nn = idx & 127;
            Xs[kk][nn] = fmaxf(x[((size_t)b*CC + kc + kk)*NN + n0 + nn], 0.f);
        }
        __syncthreads();
        #pragma unroll
        for (int kk = 0; kk < KC; kk++) {
            float wf[6], xf[8];
            const float2* wp = (const float2*)&Ws[kk][rt*6];
            float2 w0 = wp[0], w1 = wp[1], w2 = wp[2];
            wf[0]=w0.x; wf[1]=w0.y; wf[2]=w1.x; wf[3]=w1.y; wf[4]=w2.x; wf[5]=w2.y;
            const float4* xp = (const float4*)&Xs[kk][ct*8];
            float4 x0 = xp[0], x1 = xp[1];
            xf[0]=x0.x; xf[1]=x0.y; xf[2]=x0.z; xf[3]=x0.w;
            xf[4]=x1.x; xf[5]=x1.y; xf[6]=x1.z; xf[7]=x1.w;
            #pragma unroll
            for (int i = 0; i < 6; i++)
                #pragma unroll
                for (int j = 0; j < 8; j++) acc[i][j] = fmaf(wf[i], xf[j], acc[i][j]);
        }
        __syncthreads();
    }
    #pragma unroll
    for (int j = 0; j < 8; j++) {
        int n = n0 + ct*8 + j;
        float* dst = d_Bfeat + ((size_t)(b*NN + n))*C2 + rt*6;
        #pragma unroll
        for (int i = 0; i < 6; i++)
            dst[i] = fmaf(ssc[rt*6+i], acc[i][j], ssh[rt*6+i]);
    }
}

// ---------------- ball query body: 16 warps/block, 1 warp per center, pipelined ----------------
__device__ __forceinline__ void ballq_body(char* smraw, const float* __restrict__ p, int rbid) {
    unsigned short (*lists)[256] = (unsigned short (*)[256])smraw;
    int warp = threadIdx.x >> 5, lane = threadIdx.x & 31;
    int gc = rbid * 16 + warp;       // b*1024 + g
    int b = gc >> 10;
    int g = gc & 1023;

    // wait until grid built and center g sampled (this run OR byte-identical replay)
    if (lane == 0) {
        while (ld_acquire(&d_gridready[b*32]) == 0) __nanosleep(2000);
        while (ld_acquire(&d_progress[b*32]) < g + 1) __nanosleep(2000);
    }
    __syncwarp();

    int cIdx = d_samp[gc];
    const float* pb = p + (size_t)b * NN * 3;
    float cx = pb[3*cIdx], cy = pb[3*cIdx+1], cz = pb[3*cIdx+2];
    int ccx = min(9, max(0, (int)(cx * 9.99f)));
    int ccy = min(9, max(0, (int)(cy * 9.99f)));
    int ccz = min(9, max(0, (int)(cz * 9.99f)));
    const float R2 = (float)(0.1 * 0.1);
    unsigned short* lst = lists[warp];
    const int* cs = d_cellStart[b];
    int hcnt = 0;

    int ix1 = min(9, ccx+1), iy1 = min(9, ccy+1), iz1 = min(9, ccz+1);
    for (int ix = max(0, ccx-1); ix <= ix1; ix++)
    for (int iy = max(0, ccy-1); iy <= iy1; iy++)
    for (int iz = max(0, ccz-1); iz <= iz1; iz++) {
        int cell = (ix*10 + iy)*10 + iz;
        int s = cs[cell], e = cs[cell + 1];
        for (int ob = s; ob < e; ob += 32) {
            int o = ob + lane;
            bool valid = o < e;
            int pid = valid ? d_cellPts[b][o] : 0;
            float dx = __fsub_rn(cx, pb[3*pid+0]);
            float dy = __fsub_rn(cy, pb[3*pid+1]);
            float dz = __fsub_rn(cz, pb[3*pid+2]);
            float d2 = __fadd_rn(__fadd_rn(__fmul_rn(dx,dx), __fmul_rn(dy,dy)), __fmul_rn(dz,dz));
            bool hit = valid && (d2 < R2);
            unsigned mb = __ballot_sync(FULLMASK, hit);
            if (hit) {
                int ps = hcnt + __popc(mb & ((1u << lane) - 1u));
                if (ps < 256) lst[ps] = (unsigned short)pid;
            }
            hcnt += __popc(mb);
        }
    }
    __syncwarp();
    int hs = min(hcnt, 256);
    int* outp = d_nbr + (size_t)gc * NSAMP;
    if (hs <= 32) {
        unsigned rv = (lane < hs) ? (unsigned)lst[lane] : 0xffffffffu;
        unsigned first = 0;
        #pragma unroll
        for (int r = 0; r < NSAMP; r++) {
            unsigned best = __reduce_min_sync(FULLMASK, rv);
            if (r == 0) first = best;
            if (lane == r) outp[r] = (int)((r < hs) ? best : first);
            if (rv == best) rv = 0xffffffffu;
        }
    } else {
        for (int r = 0; r < NSAMP; r++) {
            unsigned lm = 0xffffffffu;
            for (int j = lane; j < hs; j += 32) lm = min(lm, (unsigned)lst[j]);
            unsigned best = __reduce_min_sync(FULLMASK, lm);
            if (lane == r) outp[r] = (int)best;
            for (int j = lane; j < hs; j += 32) if (lst[j] == best) lst[j] = 0xffff;
            __syncwarp();
        }
    }
}

// ---------------- gemmA body: 512 thr, tile 192x64, 3x8/thread, f32x2, pipelined ----------------
__device__ __forceinline__ void gemmA_body(char* smraw, const float* __restrict__ x,
                                           const float* __restrict__ Wt,
                                           const float* __restrict__ gt,
                                           const float* __restrict__ vt, int rb) {
    float (*Ws)[C2] = (float (*)[C2])smraw;
    float (*Xs)[64] = (float (*)[64])(smraw + KC*C2*4);
    int*   sidx = (int*)(smraw + KC*C2*4 + KC*64*4);
    float* ssc  = (float*)(sidx + 64);

    int b  = rb >> 4;
    int g0 = (rb & 15) * 64;
    int tid = threadIdx.x;

    if (tid == 0) {
        while (ld_acquire(&d_progress[b*32]) < g0 + 64) __nanosleep(2000);
    }
    __syncthreads();

    int rt = tid >> 3, ct = tid & 7;     // rows rt*3.., cols ct*8..
    if (tid < 64) sidx[tid] = d_samp[b*NP + g0 + tid];
    if (tid < C2) ssc[tid] = gt[tid] / sqrtf(vt[tid] + 1e-5f);
    unsigned long long acc2[3][4];
    #pragma unroll
    for (int i = 0; i < 3; i++)
        #pragma unroll
        for (int j = 0; j < 4; j++) acc2[i][j] = 0ull;

    for (int kc = 0; kc < CC; kc += KC) {
        if (tid < C2) {
            const float4* wr = (const float4*)(Wt + (size_t)tid*C2 + kc);
            #pragma unroll
            for (int q = 0; q < 8; q++) {
                float4 w = wr[q];
                Ws[q*4+0][tid] = w.x; Ws[q*4+1][tid] = w.y;
                Ws[q*4+2][tid] = w.z; Ws[q*4+3][tid] = w.w;
            }
        }
        __syncthreads();
        #pragma unroll
        for (int e = 0; e < 4; e++) {
            int idx = e*512 + tid;
            int kk = idx >> 6, nn = idx & 63;
            Xs[kk][nn] = fmaxf(x[((size_t)b*CC + kc + kk)*NN + sidx[nn]], 0.f);
        }
        __syncthreads();
        #pragma unroll
        for (int kk = 0; kk < KC; kk++) {
            float w0 = Ws[kk][rt*3+0], w1 = Ws[kk][rt*3+1], w2 = Ws[kk][rt*3+2];
            unsigned long long w2v[3];
            w2v[0] = pack2f(w0, w0); w2v[1] = pack2f(w1, w1); w2v[2] = pack2f(w2, w2);
            const unsigned long long* xp = (const unsigned long long*)&Xs[kk][ct*8];
            unsigned long long x2v[4] = {xp[0], xp[1], xp[2], xp[3]};
            #pragma unroll
            for (int i = 0; i < 3; i++)
                #pragma unroll
                for (int j = 0; j < 4; j++) FMA_F32X2(acc2[i][j], w2v[i], x2v[j]);
        }
        __syncthreads();
    }
    float acc[3][8];
    #pragma unroll
    for (int i = 0; i < 3; i++)
        #pragma unroll
        for (int j = 0; j < 4; j++) {
            unsigned lo, hi;
            UNPACK_F32X2(lo, hi, acc2[i][j]);
            acc[i][2*j] = __uint_as_float(lo);
            acc[i][2*j+1] = __uint_as_float(hi);
        }
    #pragma unroll
    for (int j = 0; j < 8; j++) {
        int g = g0 + ct*8 + j;
        float* dst = d_Afeat + ((size_t)(b*NP + g))*C2 + rt*3;
        #pragma unroll
        for (int i = 0; i < 3; i++) dst[i] = ssc[rt*3+i] * acc[i][j];
    }
}

// ---------------- fused1: FPS(8) + grid(8) + gemmB(256) + ballq(512) + gemmA(128) ----------------
__global__ __launch_bounds__(512, 1) void fused1(const float* __restrict__ p,
                                                 const float* __restrict__ x,
                                                 const float* __restrict__ Wt,
                                                 const float* __restrict__ gt,
                                                 const float* __restrict__ bt,
                                                 const float* __restrict__ mt,
                                                 const float* __restrict__ vt,
                                                 float* __restrict__ newp) {
    extern __shared__ char sm[];
    int bid = blockIdx.x;
    if (bid < 8)        fps_body(sm, p, newp, bid);
    else if (bid < 16)  gridbuild_body(sm, p, bid - 8);
    else if (bid < 272) gemmB_body(sm, x, Wt, gt, bt, mt, vt, bid - 16);
    else if (bid < 784) ballq_body(sm, p, bid - 272);
    else                gemmA_body(sm, x, Wt, gt, vt, bid - 784);
}

// ---------------- aggregation: 4 centers/block, float4 channels ----------------
__global__ __launch_bounds__(192) void agg_kernel(const float* __restrict__ p,
                                                  const float* __restrict__ newp) {
    int bg0 = blockIdx.x * 4;
    int b   = bg0 >> 10;
    int tid = threadIdx.x;
    __shared__ int   snbr[4][16];
    __shared__ float sctr[4][3];
    __shared__ float sp[4][16][3];
    if (tid < 64) snbr[tid >> 4][tid & 15] = d_nbr[(size_t)bg0*NSAMP + tid];
    if (tid < 12) sctr[tid / 3][tid % 3] = newp[(size_t)bg0*3 + tid];
    __syncthreads();
    {
        int ci = tid / 48, rem = tid % 48, s = rem / 3, d = rem % 3;
        sp[ci][s][d] = p[((size_t)(b*NN + snbr[ci][s]))*3 + d];
    }
    __syncthreads();

    int ci = tid / 48, t = tid % 48;
    int ch0 = t * 4;
    int bg  = bg0 + ci;
    int dim = ch0 >> 6;
    int r0  = ch0 & 63;
    bool isSin = r0 < 32;
    int j0 = isSin ? r0 : (r0 - 32);
    float pm[4];
    #pragma unroll
    for (int q = 0; q < 4; q++)
        pm[q] = 50.0f * exp2f(-(float)(j0 + q) * (8.965784284662087f / 32.0f));
    float ctr = sctr[ci][dim];
    float4 a4 = *(const float4*)&d_Afeat[(size_t)bg*C2 + ch0];

    int   ni[16];
    float dpd[16];
    #pragma unroll
    for (int s = 0; s < NSAMP; s++) {
        ni[s]  = snbr[ci][s];
        dpd[s] = sp[ci][s][dim] - ctr;
    }

    float vmax[4], vsum[4];
    #pragma unroll
    for (int q = 0; q < 4; q++) { vmax[q] = -INFINITY; vsum[q] = 0.f; }

    #pragma unroll 4
    for (int s = 0; s < NSAMP; s++) {
        float4 bv = *(const float4*)&d_Bfeat[((size_t)(b*NN + ni[s]))*C2 + ch0];
        float tq[4];
        tq[0] = fmaxf(a4.x + bv.x, 0.f);
        tq[1] = fmaxf(a4.y + bv.y, 0.f);
        tq[2] = fmaxf(a4.z + bv.z, 0.f);
        tq[3] = fmaxf(a4.w + bv.w, 0.f);
        #pragma unroll
        for (int q = 0; q < 4; q++) {
            float pos = dpd[s] * pm[q];
            float e = isSin ? __sinf(pos) : __cosf(pos);
            float ag = fmaf(tq[q], e, e);
            vmax[q] = fmaxf(vmax[q], ag);
            vsum[q] += ag;
        }
    }
    float4 outv;
    outv.x = fmaxf(vmax[0] + vsum[0]*(1.0f/16.0f), 0.f);
    outv.y = fmaxf(vmax[1] + vsum[1]*(1.0f/16.0f), 0.f);
    outv.z = fmaxf(vmax[2] + vsum[2]*(1.0f/16.0f), 0.f);
    outv.w = fmaxf(vmax[3] + vsum[3]*(1.0f/16.0f), 0.f);
    *(float4*)&d_Pool[(size_t)bg*C2 + ch0] = outv;
}

// ---------------- final conv: 512 blocks, 192x16 tiles, f32x2 ----------------
__global__ __launch_bounds__(192) void gemm2_kernel(const float* __restrict__ Wc,
                                                    const float* __restrict__ gc,
                                                    const float* __restrict__ bc,
                                                    const float* __restrict__ mc,
                                                    const float* __restrict__ vc,
                                                    float* __restrict__ out) {
    __shared__ __align__(16) float Ws[KC][C2];
    __shared__ __align__(16) float Xs[KC][16];
    __shared__ float ssc[C2], ssh[C2];
    int col0 = blockIdx.x * 16;
    int b  = col0 >> 10;
    int g0 = col0 & 1023;
    int tid = threadIdx.x;
    int rt = tid >> 1, ct = tid & 1;     // rows rt*2.., cols ct*8..
    {
        float st = gc[tid] / sqrtf(vc[tid] + 1e-5f);
        ssc[tid] = st;
        ssh[tid] = bc[tid] - mc[tid]*st;
    }
    unsigned long long acc2[2][4];
    #pragma unroll
    for (int i = 0; i < 2; i++)
        #pragma unroll
        for (int j = 0; j < 4; j++) acc2[i][j] = 0ull;

    for (int kc = 0; kc < C2; kc += KC) {
        {
            const float4* wr = (const float4*)(Wc + (size_t)tid*C2 + kc);
            #pragma unroll
            for (int q = 0; q < 8; q++) {
                float4 w = wr[q];
                Ws[q*4+0][tid] = w.x; Ws[q*4+1][tid] = w.y;
                Ws[q*4+2][tid] = w.z; Ws[q*4+3][tid] = w.w;
            }
        }
        if (tid < 128) {
            int col = tid & 15, kq = tid >> 4;
            float4 v = *(const float4*)(d_Pool + (size_t)(col0 + col)*C2 + kc + kq*4);
            Xs[kq*4+0][col] = v.x;
            Xs[kq*4+1][col] = v.y;
            Xs[kq*4+2][col] = v.z;
            Xs[kq*4+3][col] = v.w;
        }
        __syncthreads();
        #pragma unroll
        for (int kk = 0; kk < KC; kk++) {
            float2 w = *(const float2*)&Ws[kk][rt*2];
            unsigned long long w2v[2];
            w2v[0] = pack2f(w.x, w.x);
            w2v[1] = pack2f(w.y, w.y);
            const unsigned long long* xp = (const unsigned long long*)&Xs[kk][ct*8];
            unsigned long long x2v[4] = {xp[0], xp[1], xp[2], xp[3]};
            #pragma unroll
            for (int i = 0; i < 2; i++)
                #pragma unroll
                for (int j = 0; j < 4; j++) FMA_F32X2(acc2[i][j], w2v[i], x2v[j]);
        }
        __syncthreads();
    }
    #pragma unroll
    for (int i = 0; i < 2; i++) {
        int o = rt*2 + i;
        float vals[8];
        #pragma unroll
        for (int j = 0; j < 4; j++) {
            unsigned lo, hi;
            UNPACK_F32X2(lo, hi, acc2[i][j]);
            vals[2*j]   = __uint_as_float(lo);
            vals[2*j+1] = __uint_as_float(hi);
        }
        float* dst = out + (size_t)b*C2*NP + (size_t)o*NP + g0 + ct*8;
        #pragma unroll
        for (int j = 0; j < 8; j++)
            dst[j] = fmaxf(fmaf(ssc[o], vals[j], ssh[o]), 0.f);
    }
}

extern "C" void kernel_launch(void* const* d_in, const int* in_sizes, int n_in,
                              void* d_out, int out_size) {
    const float* p  = (const float*)d_in[0];
    const float* x  = (const float*)d_in[1];
    const float* Wt = (const float*)d_in[2];
    const float* gt = (const float*)d_in[3];
    const float* bt = (const float*)d_in[4];
    const float* mt = (const float*)d_in[5];
    const float* vt = (const float*)d_in[6];
    const float* Wc = (const float*)d_in[7];
    const float* gc = (const float*)d_in[8];
    const float* bc = (const float*)d_in[9];
    const float* mc = (const float*)d_in[10];
    const float* vc = (const float*)d_in[11];

    float* newp = (float*)d_out;                  // [8,1024,3]
    float* out  = (float*)d_out + BB*NP*3;        // [8,192,1024]

    // fused1 smem: FPS layout = 3*4096*4 + 4096*2 + 2*512*4 + 4096*2 + 64*4
    const int FUSED1_SMEM = 3*NN*4 + NN*2 + 2*512*4 + NN*2 + 64*4;  // 69888
    cudaFuncSetAttribute(fused1, cudaFuncAttributeMaxDynamicSharedMemorySize, FUSED1_SMEM);

    fused1<<<912, 512, FUSED1_SMEM>>>(p, x, Wt, gt, bt, mt, vt, newp);
    agg_kernel<<<(BB*NP)/4, 192>>>(p, newp);
    gemm2_kernel<<<(BB*NP)/16, 192>>>(Wc, gc, bc, mc, vc, out);
}

// round 10
// speedup vs baseline: 1.5869x; 1.5869x over previous
#include <cuda_runtime.h>
#include <math.h>
#include <stdint.h>

#define BB 8
#define NN 4096
#define CC 96
#define C2 192
#define NP 1024
#define NSAMP 16
#define FULLMASK 0xffffffffu
#define KC 32

// ---- packed f32x2 helpers (exact per-lane IEEE RN, sm_103a) ----
#define MUL_F32X2(out, a, b) \
    asm("mul.rn.f32x2 %0, %1, %2;" : "=l"(out) : "l"(a), "l"(b))
#define ADD_F32X2(out, a, b) \
    asm("add.rn.f32x2 %0, %1, %2;" : "=l"(out) : "l"(a), "l"(b))
#define FMA_F32X2(d, a, b) \
    asm("fma.rn.f32x2 %0, %1, %2, %0;" : "+l"(d) : "l"(a), "l"(b))
#define UNPACK_F32X2(lo, hi, in) \
    asm("mov.b64 {%0, %1}, %2;" : "=r"(lo), "=r"(hi) : "l"(in))

__device__ __forceinline__ unsigned long long pack2u(unsigned lo, unsigned hi) {
    unsigned long long r;
    asm("mov.b64 %0, {%1, %2};" : "=l"(r) : "r"(lo), "r"(hi));
    return r;
}
__device__ __forceinline__ unsigned long long pack2f(float lo, float hi) {
    return pack2u(__float_as_uint(lo), __float_as_uint(hi));
}

// ---------------- scratch ----------------
__device__ int   d_samp[BB*NP];
__device__ int   d_nbr[BB*NP*NSAMP];
__device__ float d_Bfeat[BB*NN*C2];    // [b][n][c]
__device__ float d_Afeat[BB*NP*C2];    // [b][g][c]
__device__ float d_Pool[BB*NP*C2];     // [b][g][c]
__device__ int   d_cellStart[BB][1001];
__device__ int   d_cellPts[BB][NN];

__device__ __forceinline__ int cellof(float x, float y, float z) {
    int ix = min(9, max(0, (int)(x * 9.99f)));
    int iy = min(9, max(0, (int)(y * 9.99f)));
    int iz = min(9, max(0, (int)(z * 9.99f)));
    return (ix * 10 + iy) * 10 + iz;
}

__device__ __forceinline__ int spread3(int b) {
    return (b & 1) | ((b & 2) << 2) | ((b & 4) << 4);
}

// ---------------- FPS body: 512 threads, 8 pts/thread, warp-bbox pruning ----------------
// Exactness: a warp skips ONLY when lb2(warp bbox)*0.999 >= warp_max(mind)
// (the prior iteration's stage-1 reduction value). Then every distance in the
// warp satisfies fl(d_i) >= lb2*0.999 >= mind_i (fp margin >100x rounding), so
// all minds are provably unchanged and cached (vmax, argpack) stay valid.
// Tie keys = origidx*4096+sortedpos => min original index (jnp.argmax order).
__device__ __forceinline__ void fps_body(char* smraw, const float* __restrict__ p,
                                         float* __restrict__ newp, int b) {
    float* ssx = (float*)smraw;                              // [4096] sorted coords
    float* ssy = ssx + NN;
    float* ssz = ssy + NN;
    unsigned short* sorig = (unsigned short*)(ssz + NN);     // [4096] orig index
    int* scnt  = (int*)(sorig + NN);                         // [512]
    int* scnt2 = scnt + 512;                                 // [512]
    unsigned short* scell = (unsigned short*)(scnt2 + 512);  // [4096]
    unsigned* sred = (unsigned*)(scell + NN);                // [64]

    int tid = threadIdx.x, lane = tid & 31, warp = tid >> 5;
    const float* pb = p + (size_t)b * NN * 3;

    // ---- counting sort into 512 Morton cells ----
    for (int i = tid; i < 512; i += 512) scnt[i] = 0;
    __syncthreads();
    for (int i = tid; i < NN; i += 512) {
        float xx = pb[3*i], yy = pb[3*i+1], zz = pb[3*i+2];
        int ix = min(7, max(0, (int)(xx * 8.0f)));
        int iy = min(7, max(0, (int)(yy * 8.0f)));
        int iz = min(7, max(0, (int)(zz * 8.0f)));
        int cell = (spread3(ix) << 2) | (spread3(iy) << 1) | spread3(iz);
        scell[i] = (unsigned short)cell;
        atomicAdd(&scnt[cell], 1);
    }
    __syncthreads();
    {
        int* src = scnt; int* dst = scnt2;
        for (int off = 1; off < 512; off <<= 1) {
            for (int i = tid; i < 512; i += 512)
                dst[i] = src[i] + ((i >= off) ? src[i - off] : 0);
            __syncthreads();
            int* t = src; src = dst; dst = t;
        }
        for (int i = tid; i < 512; i += 512)
            dst[i] = (i == 0) ? 0 : src[i-1];
        __syncthreads();
        for (int i = tid; i < NN; i += 512) {
            int cell = scell[i];
            int pos = atomicAdd(&dst[cell], 1);
            ssx[pos] = pb[3*i];
            ssy[pos] = pb[3*i+1];
            ssz[pos] = pb[3*i+2];
            sorig[pos] = (unsigned short)i;
        }
    }
    __syncthreads();

    // ---- my chunk: 8 sorted points ----
    const int base = tid * 8;
    float vx[8], vy[8], vz[8];
    #pragma unroll
    for (int i = 0; i < 8; i++) {
        vx[i] = ssx[base + i];
        vy[i] = ssy[base + i];
        vz[i] = ssz[base + i];
    }
    unsigned long long pxp[4], pyp[4], pzp[4];
    #pragma unroll
    for (int j = 0; j < 4; j++) {
        pxp[j] = pack2f(vx[2*j], vx[2*j+1]);
        pyp[j] = pack2f(vy[2*j], vy[2*j+1]);
        pzp[j] = pack2f(vz[2*j], vz[2*j+1]);
    }
    // lane bbox then warp bbox (union over lanes), one-time
    float bxlo = vx[0], bxhi = vx[0], bylo = vy[0], byhi = vy[0], bzlo = vz[0], bzhi = vz[0];
    #pragma unroll
    for (int i = 1; i < 8; i++) {
        bxlo = fminf(bxlo, vx[i]); bxhi = fmaxf(bxhi, vx[i]);
        bylo = fminf(bylo, vy[i]); byhi = fmaxf(byhi, vy[i]);
        bzlo = fminf(bzlo, vz[i]); bzhi = fmaxf(bzhi, vz[i]);
    }
    #pragma unroll
    for (int o = 16; o; o >>= 1) {
        bxlo = fminf(bxlo, __shfl_xor_sync(FULLMASK, bxlo, o));
        bxhi = fmaxf(bxhi, __shfl_xor_sync(FULLMASK, bxhi, o));
        bylo = fminf(bylo, __shfl_xor_sync(FULLMASK, bylo, o));
        byhi = fmaxf(byhi, __shfl_xor_sync(FULLMASK, byhi, o));
        bzlo = fminf(bzlo, __shfl_xor_sync(FULLMASK, bzlo, o));
        bzhi = fmaxf(bzhi, __shfl_xor_sync(FULLMASK, bzhi, o));
    }
    unsigned opack[8];
    #pragma unroll
    for (int i = 0; i < 8; i++)
        opack[i] = ((unsigned)sorig[base + i] << 12) | (unsigned)(base + i);

    float mind[8];
    #pragma unroll
    for (int i = 0; i < 8; i++) mind[i] = 1e10f;
    float vmaxf = 1e10f;
    unsigned apack = opack[0];
    unsigned wm = __float_as_uint(1e10f);     // warp max of mind (from prior reduction)

    float lx = pb[0], ly = pb[1], lz = pb[2];
    if (tid == 0) {
        d_samp[b*NP + 0] = 0;
        newp[(size_t)(b*NP)*3 + 0] = lx;
        newp[(size_t)(b*NP)*3 + 1] = ly;
        newp[(size_t)(b*NP)*3 + 2] = lz;
    }

    for (int k = 1; k < NP; k++) {
        // uniform warp-bbox test against warp's current mind-max (wm)
        float tx = fmaxf(fmaxf(bxlo - lx, lx - bxhi), 0.f);
        float ty = fmaxf(fmaxf(bylo - ly, ly - byhi), 0.f);
        float tz = fmaxf(fmaxf(bzlo - lz, lz - bzhi), 0.f);
        float lb2 = tx*tx + ty*ty + tz*tz;
        if (lb2 * 0.999f < __uint_as_float(wm)) {
            unsigned long long nlx = pack2f(-lx, -lx);
            unsigned long long nly = pack2f(-ly, -ly);
            unsigned long long nlz = pack2f(-lz, -lz);
            #pragma unroll
            for (int j = 0; j < 4; j++) {
                unsigned long long dx, dy, dz, t1, t2, t3, s;
                ADD_F32X2(dx, pxp[j], nlx);
                ADD_F32X2(dy, pyp[j], nly);
                ADD_F32X2(dz, pzp[j], nlz);
                MUL_F32X2(t1, dx, dx);
                MUL_F32X2(t2, dy, dy);
                MUL_F32X2(t3, dz, dz);
                ADD_F32X2(s, t1, t2);
                ADD_F32X2(s, s, t3);
                unsigned lo, hi;
                UNPACK_F32X2(lo, hi, s);
                mind[2*j]   = fminf(mind[2*j],   __uint_as_float(lo));
                mind[2*j+1] = fminf(mind[2*j+1], __uint_as_float(hi));
            }
            float a0 = fmaxf(mind[0], mind[1]), a1 = fmaxf(mind[2], mind[3]);
            float a2 = fmaxf(mind[4], mind[5]), a3 = fmaxf(mind[6], mind[7]);
            float v = fmaxf(fmaxf(a0, a1), fmaxf(a2, a3));
            unsigned ci[8];
            #pragma unroll
            for (int i = 0; i < 8; i++)
                ci[i] = (mind[i] == v) ? opack[i] : 0xffffffffu;
            #pragma unroll
            for (int s2 = 4; s2; s2 >>= 1)
                #pragma unroll
                for (int i = 0; i < 4; i++)
                    if (i < s2) ci[i] = min(ci[i], ci[i + s2]);
            vmaxf = v;
            apack = ci[0];
        }
        // warp reduce (dist >= 0 so uint order on bits == float order)
        unsigned vb = __float_as_uint(vmaxf);
        unsigned m = __reduce_max_sync(FULLMASK, vb);
        unsigned cand = (vb == m) ? apack : 0xffffffffu;
        unsigned l = __reduce_min_sync(FULLMASK, cand);
        wm = m;

        int par = (k & 1) << 4;
        if (lane == 0) { sred[par + warp] = m; sred[32 + par + warp] = l; }
        __syncthreads();
        unsigned v16 = (lane < 16) ? sred[par + lane] : 0u;
        unsigned bm = __reduce_max_sync(FULLMASK, v16);
        unsigned i16 = (lane < 16 && v16 == bm) ? sred[32 + par + lane] : 0xffffffffu;
        unsigned wp = __reduce_min_sync(FULLMASK, i16);

        int spos = (int)(wp & 4095u);
        lx = ssx[spos]; ly = ssy[spos]; lz = ssz[spos];
        if (tid == 0) {
            d_samp[b*NP + k] = (int)(wp >> 12);
            newp[(size_t)(b*NP + k)*3 + 0] = lx;
            newp[(size_t)(b*NP + k)*3 + 1] = ly;
            newp[(size_t)(b*NP + k)*3 + 2] = lz;
        }
    }
}

// ---------------- grid build body: 512 threads, 1 block per batch ----------------
__device__ __forceinline__ void gridbuild_body(char* smraw, const float* __restrict__ p, int b) {
    int* a  = (int*)smraw;        // 1024
    int* bb = a + 1024;           // 1024
    int tid = threadIdx.x;
    const float* pb = p + (size_t)b * NN * 3;

    for (int i = tid; i < 1024; i += 512) a[i] = 0;
    __syncthreads();

    int mycell[8];
    #pragma unroll
    for (int e = 0; e < 8; e++) {
        int i = e*512 + tid;
        int c = cellof(pb[3*i], pb[3*i+1], pb[3*i+2]);
        mycell[e] = c;
        atomicAdd(&a[c], 1);
    }
    __syncthreads();

    int* src = a; int* dst = bb;
    for (int off = 1; off < 1024; off <<= 1) {
        for (int i = tid; i < 1024; i += 512)
            dst[i] = src[i] + ((i >= off) ? src[i - off] : 0);
        __syncthreads();
        int* t = src; src = dst; dst = t;
    }
    for (int i = tid; i <= 1000; i += 512)
        d_cellStart[b][i] = (i == 0) ? 0 : src[i-1];
    for (int i = tid; i < 1000; i += 512)
        dst[i] = (i == 0) ? 0 : src[i-1];       // cursors
    __syncthreads();

    #pragma unroll
    for (int e = 0; e < 8; e++) {
        int i = e*512 + tid;
        int slot = atomicAdd(&dst[mycell[e]], 1);
        d_cellPts[b][slot] = i;
    }
}

// ---------------- gemmB body: 512 thr, tile 192x128, thread tile 6x8 ----------------
__device__ __forceinline__ void gemmB_body(char* smraw, const float* __restrict__ x,
                                           const float* __restrict__ Wt,
                                           const float* __restrict__ gt, const float* __restrict__ bt,
                                           const float* __restrict__ mt, const float* __restrict__ vt,
                                           int rb) {
    float (*Ws)[C2]  = (float (*)[C2])smraw;                      // [32][192]
    float (*Xs)[128] = (float (*)[128])(smraw + KC*C2*4);         // [32][128]
    float* ssc = (float*)(smraw + KC*C2*4 + KC*128*4);            // [192]
    float* ssh = ssc + C2;

    int tid = threadIdx.x;
    int b = rb >> 5, n0 = (rb & 31) * 128;
    if (tid < C2) {
        float st = gt[tid] / sqrtf(vt[tid] + 1e-5f);
        ssc[tid] = st;
        ssh[tid] = bt[tid] - mt[tid]*st;
    }
    int rt = tid >> 4, ct = tid & 15;      // rows rt*6.., cols ct*8..
    float acc[6][8];
    #pragma unroll
    for (int i = 0; i < 6; i++)
        #pragma unroll
        for (int j = 0; j < 8; j++) acc[i][j] = 0.f;

    for (int kc = 0; kc < CC; kc += KC) {
        if (tid < C2) {
            const float4* wr = (const float4*)(Wt + (size_t)tid*C2 + CC + kc);
            #pragma unroll
            for (int q = 0; q < 8; q++) {
                float4 w = wr[q];
                Ws[q*4+0][tid] = w.x; Ws[q*4+1][tid] = w.y;
                Ws[q*4+2][tid] = w.z; Ws[q*4+3][tid] = w.w;
            }
        }
        #pragma unroll
        for (int e = 0; e < 8; e++) {
            int idx = e*512 + tid;
            int kk = idx >> 7, nn = idx & 127;
            Xs[kk][nn] = fmaxf(x[((size_t)b*CC + kc + kk)*NN + n0 + nn], 0.f);
        }
        __syncthreads();
        #pragma unroll
        for (int kk = 0; kk < KC; kk++) {
            float wf[6], xf[8];
            const float2* wp = (const float2*)&Ws[kk][rt*6];
            float2 w0 = wp[0], w1 = wp[1], w2 = wp[2];
            wf[0]=w0.x; wf[1]=w0.y; wf[2]=w1.x; wf[3]=w1.y; wf[4]=w2.x; wf[5]=w2.y;
            const float4* xp = (const float4*)&Xs[kk][ct*8];
            float4 x0 = xp[0], x1 = xp[1];
            xf[0]=x0.x; xf[1]=x0.y; xf[2]=x0.z; xf[3]=x0.w;
            xf[4]=x1.x; xf[5]=x1.y; xf[6]=x1.z; xf[7]=x1.w;
            #pragma unroll
            for (int i = 0; i < 6; i++)
                #pragma unroll
                for (int j = 0; j < 8; j++) acc[i][j] = fmaf(wf[i], xf[j], acc[i][j]);
        }
        __syncthreads();
    }
    #pragma unroll
    for (int j = 0; j < 8; j++) {
        int n = n0 + ct*8 + j;
        float* dst = d_Bfeat + ((size_t)(b*NN + n))*C2 + rt*6;
        #pragma unroll
        for (int i = 0; i < 6; i++)
            dst[i] = fmaf(ssc[rt*6+i], acc[i][j], ssh[rt*6+i]);
    }
}

// ---------------- fused1: blocks 0-7 FPS, 8-15 grid build, 16-271 gemmB ----------------
__global__ __launch_bounds__(512, 1) void fused1(const float* __restrict__ p,
                                                 const float* __restrict__ x,
                                                 const float* __restrict__ Wt,
                                                 const float* __restrict__ gt,
                                                 const float* __restrict__ bt,
                                                 const float* __restrict__ mt,
                                                 const float* __restrict__ vt,
                                                 float* __restrict__ newp) {
    extern __shared__ char sm[];
    int bid = blockIdx.x;
    if (bid < 8)       fps_body(sm, p, newp, bid);
    else if (bid < 16) gridbuild_body(sm, p, bid - 8);
    else               gemmB_body(sm, x, Wt, gt, bt, mt, vt, bid - 16);
}

// ---------------- ball query body: 8 warps/block, 1 warp per center ----------------
__device__ __forceinline__ void ballq_body(char* smraw, const float* __restrict__ p, int bid) {
    unsigned short (*lists)[256] = (unsigned short (*)[256])smraw;
    int warp = threadIdx.x >> 5, lane = threadIdx.x & 31;
    int gc = bid * 8 + warp;       // b*1024 + g
    int b = gc >> 10;
    int cIdx = d_samp[gc];
    const float* pb = p + (size_t)b * NN * 3;
    float cx = pb[3*cIdx], cy = pb[3*cIdx+1], cz = pb[3*cIdx+2];
    int ccx = min(9, max(0, (int)(cx * 9.99f)));
    int ccy = min(9, max(0, (int)(cy * 9.99f)));
    int ccz = min(9, max(0, (int)(cz * 9.99f)));
    const float R2 = (float)(0.1 * 0.1);
    unsigned short* lst = lists[warp];
    const int* cs = d_cellStart[b];
    int hcnt = 0;

    int ix1 = min(9, ccx+1), iy1 = min(9, ccy+1), iz1 = min(9, ccz+1);
    for (int ix = max(0, ccx-1); ix <= ix1; ix++)
    for (int iy = max(0, ccy-1); iy <= iy1; iy++)
    for (int iz = max(0, ccz-1); iz <= iz1; iz++) {
        int cell = (ix*10 + iy)*10 + iz;
        int s = cs[cell], e = cs[cell + 1];
        for (int ob = s; ob < e; ob += 32) {
            int o = ob + lane;
            bool valid = o < e;
            int pid = valid ? d_cellPts[b][o] : 0;
            float dx = __fsub_rn(cx, pb[3*pid+0]);
            float dy = __fsub_rn(cy, pb[3*pid+1]);
            float dz = __fsub_rn(cz, pb[3*pid+2]);
            float d2 = __fadd_rn(__fadd_rn(__fmul_rn(dx,dx), __fmul_rn(dy,dy)), __fmul_rn(dz,dz));
            bool hit = valid && (d2 < R2);
            unsigned mb = __ballot_sync(FULLMASK, hit);
            if (hit) {
                int ps = hcnt + __popc(mb & ((1u << lane) - 1u));
                if (ps < 256) lst[ps] = (unsigned short)pid;
            }
            hcnt += __popc(mb);
        }
    }
    __syncwarp();
    int hs = min(hcnt, 256);
    int* outp = d_nbr + (size_t)gc * NSAMP;
    if (hs <= 32) {
        unsigned rv = (lane < hs) ? (unsigned)lst[lane] : 0xffffffffu;
        unsigned first = 0;
        #pragma unroll
        for (int r = 0; r < NSAMP; r++) {
            unsigned best = __reduce_min_sync(FULLMASK, rv);
            if (r == 0) first = best;
            if (lane == r) outp[r] = (int)((r < hs) ? best : first);
            if (rv == best) rv = 0xffffffffu;
        }
    } else {
        for (int r = 0; r < NSAMP; r++) {
            unsigned lm = 0xffffffffu;
            for (int j = lane; j < hs; j += 32) lm = min(lm, (unsigned)lst[j]);
            unsigned best = __reduce_min_sync(FULLMASK, lm);
            if (lane == r) outp[r] = (int)best;
            for (int j = lane; j < hs; j += 32) if (lst[j] == best) lst[j] = 0xffff;
            __syncwarp();
        }
    }
}

// ---------------- gemmA body: 256 thr, tile 192x64, 6x8/thread, f32x2 ----------------
__device__ __forceinline__ void gemmA_body(char* smraw, const float* __restrict__ x,
                                           const float* __restrict__ Wt,
                                           const float* __restrict__ gt,
                                           const float* __restrict__ vt, int rb) {
    float (*Ws)[C2] = (float (*)[C2])smraw;                  // [32][192]
    float (*Xs)[64] = (float (*)[64])(smraw + KC*C2*4);      // [32][64]
    int*   sidx = (int*)(smraw + KC*C2*4 + KC*64*4);         // [64]
    float* ssc  = (float*)(sidx + 64);                       // [192]

    int b  = rb >> 4;
    int g0 = (rb & 15) * 64;
    int tid = threadIdx.x;
    int rt = tid >> 3, ct = tid & 7;
    if (tid < 64) sidx[tid] = d_samp[b*NP + g0 + tid];
    if (tid < C2) ssc[tid] = gt[tid] / sqrtf(vt[tid] + 1e-5f);
    unsigned long long acc2[6][4];
    #pragma unroll
    for (int i = 0; i < 6; i++)
        #pragma unroll
        for (int j = 0; j < 4; j++) acc2[i][j] = 0ull;

    for (int kc = 0; kc < CC; kc += KC) {
        if (tid < C2) {
            const float4* wr = (const float4*)(Wt + (size_t)tid*C2 + kc);
            #pragma unroll
            for (int q = 0; q < 8; q++) {
                float4 w = wr[q];
                Ws[q*4+0][tid] = w.x; Ws[q*4+1][tid] = w.y;
                Ws[q*4+2][tid] = w.z; Ws[q*4+3][tid] = w.w;
            }
        }
        __syncthreads();
        #pragma unroll
        for (int e = 0; e < 8; e++) {
            int idx = e*256 + tid;
            int kk = idx >> 6, nn = idx & 63;
            Xs[kk][nn] = fmaxf(x[((size_t)b*CC + kc + kk)*NN + sidx[nn]], 0.f);
        }
        __syncthreads();
        #pragma unroll
        for (int kk = 0; kk < KC; kk++) {
            const float2* wp = (const float2*)&Ws[kk][rt*6];
            float2 w0 = wp[0], w1 = wp[1], w2 = wp[2];
            unsigned long long w2v[6];
            w2v[0] = pack2f(w0.x, w0.x); w2v[1] = pack2f(w0.y, w0.y);
            w2v[2] = pack2f(w1.x, w1.x); w2v[3] = pack2f(w1.y, w1.y);
            w2v[4] = pack2f(w2.x, w2.x); w2v[5] = pack2f(w2.y, w2.y);
            const unsigned long long* xp = (const unsigned long long*)&Xs[kk][ct*8];
            unsigned long long x2v[4] = {xp[0], xp[1], xp[2], xp[3]};
            #pragma unroll
            for (int i = 0; i < 6; i++)
                #pragma unroll
                for (int j = 0; j < 4; j++) FMA_F32X2(acc2[i][j], w2v[i], x2v[j]);
        }
        __syncthreads();
    }
    float acc[6][8];
    #pragma unroll
    for (int i = 0; i < 6; i++)
        #pragma unroll
        for (int j = 0; j < 4; j++) {
            unsigned lo, hi;
            UNPACK_F32X2(lo, hi, acc2[i][j]);
            acc[i][2*j] = __uint_as_float(lo);
            acc[i][2*j+1] = __uint_as_float(hi);
        }
    #pragma unroll
    for (int j = 0; j < 8; j++) {
        int g = g0 + ct*8 + j;
        float* dst = d_Afeat + ((size_t)(b*NP + g))*C2 + rt*6;
        #pragma unroll
        for (int i = 0; i < 6; i++) dst[i] = ssc[rt*6+i] * acc[i][j];
    }
}

// ---------------- fused2: blocks 0-1023 ballq, 1024-1151 gemmA ----------------
__global__ __launch_bounds__(256) void fused2(const float* __restrict__ p,
                                              const float* __restrict__ x,
                                              const float* __restrict__ Wt,
                                              const float* __restrict__ gt,
                                              const float* __restrict__ vt) {
    extern __shared__ char sm[];
    int bid = blockIdx.x;
    if (bid < 1024) ballq_body(sm, p, bid);
    else            gemmA_body(sm, x, Wt, gt, vt, bid - 1024);
}

// ---------------- aggregation: 4 centers/block, float4 channels ----------------
__global__ __launch_bounds__(192) void agg_kernel(const float* __restrict__ p,
                                                  const float* __restrict__ newp) {
    int bg0 = blockIdx.x * 4;
    int b   = bg0 >> 10;
    int tid = threadIdx.x;
    __shared__ int   snbr[4][16];
    __shared__ float sctr[4][3];
    __shared__ float sp[4][16][3];
    if (tid < 64) snbr[tid >> 4][tid & 15] = d_nbr[(size_t)bg0*NSAMP + tid];
    if (tid < 12) sctr[tid / 3][tid % 3] = newp[(size_t)bg0*3 + tid];
    __syncthreads();
    {
        int ci = tid / 48, rem = tid % 48, s = rem / 3, d = rem % 3;
        sp[ci][s][d] = p[((size_t)(b*NN + snbr[ci][s]))*3 + d];
    }
    __syncthreads();

    int ci = tid / 48, t = tid % 48;
    int ch0 = t * 4;
    int bg  = bg0 + ci;
    int dim = ch0 >> 6;
    int r0  = ch0 & 63;
    bool isSin = r0 < 32;
    int j0 = isSin ? r0 : (r0 - 32);
    float pm[4];
    #pragma unroll
    for (int q = 0; q < 4; q++)
        pm[q] = 50.0f * exp2f(-(float)(j0 + q) * (8.965784284662087f / 32.0f));
    float ctr = sctr[ci][dim];
    float4 a4 = *(const float4*)&d_Afeat[(size_t)bg*C2 + ch0];

    int   ni[16];
    float dpd[16];
    #pragma unroll
    for (int s = 0; s < NSAMP; s++) {
        ni[s]  = snbr[ci][s];
        dpd[s] = sp[ci][s][dim] - ctr;
    }

    float vmax[4], vsum[4];
    #pragma unroll
    for (int q = 0; q < 4; q++) { vmax[q] = -INFINITY; vsum[q] = 0.f; }

    #pragma unroll 4
    for (int s = 0; s < NSAMP; s++) {
        float4 bv = *(const float4*)&d_Bfeat[((size_t)(b*NN + ni[s]))*C2 + ch0];
        float tq[4];
        tq[0] = fmaxf(a4.x + bv.x, 0.f);
        tq[1] = fmaxf(a4.y + bv.y, 0.f);
        tq[2] = fmaxf(a4.z + bv.z, 0.f);
        tq[3] = fmaxf(a4.w + bv.w, 0.f);
        #pragma unroll
        for (int q = 0; q < 4; q++) {
            float pos = dpd[s] * pm[q];
            float e = isSin ? __sinf(pos) : __cosf(pos);
            float ag = fmaf(tq[q], e, e);
            vmax[q] = fmaxf(vmax[q], ag);
            vsum[q] += ag;
        }
    }
    float4 outv;
    outv.x = fmaxf(vmax[0] + vsum[0]*(1.0f/16.0f), 0.f);
    outv.y = fmaxf(vmax[1] + vsum[1]*(1.0f/16.0f), 0.f);
    outv.z = fmaxf(vmax[2] + vsum[2]*(1.0f/16.0f), 0.f);
    outv.w = fmaxf(vmax[3] + vsum[3]*(1.0f/16.0f), 0.f);
    *(float4*)&d_Pool[(size_t)bg*C2 + ch0] = outv;
}

// ---------------- final conv: 512 blocks, 192x16 tiles, f32x2 ----------------
__global__ __launch_bounds__(192) void gemm2_kernel(const float* __restrict__ Wc,
                                                    const float* __restrict__ gc,
                                                    const float* __restrict__ bc,
                                                    const float* __restrict__ mc,
                                                    const float* __restrict__ vc,
                                                    float* __restrict__ out) {
    __shared__ __align__(16) float Ws[KC][C2];
    __shared__ __align__(16) float Xs[KC][16];
    __shared__ float ssc[C2], ssh[C2];
    int col0 = blockIdx.x * 16;
    int b  = col0 >> 10;
    int g0 = col0 & 1023;
    int tid = threadIdx.x;
    int rt = tid >> 1, ct = tid & 1;     // rows rt*2.., cols ct*8..
    {
        float st = gc[tid] / sqrtf(vc[tid] + 1e-5f);
        ssc[tid] = st;
        ssh[tid] = bc[tid] - mc[tid]*st;
    }
    unsigned long long acc2[2][4];
    #pragma unroll
    for (int i = 0; i < 2; i++)
        #pragma unroll
        for (int j = 0; j < 4; j++) acc2[i][j] = 0ull;

    for (int kc = 0; kc < C2; kc += KC) {
        {
            const float4* wr = (const float4*)(Wc + (size_t)tid*C2 + kc);
            #pragma unroll
            for (int q = 0; q < 8; q++) {
                float4 w = wr[q];
                Ws[q*4+0][tid] = w.x; Ws[q*4+1][tid] = w.y;
                Ws[q*4+2][tid] = w.z; Ws[q*4+3][tid] = w.w;
            }
        }
        if (tid < 128) {
            int col = tid & 15, kq = tid >> 4;
            float4 v = *(const float4*)(d_Pool + (size_t)(col0 + col)*C2 + kc + kq*4);
            Xs[kq*4+0][col] = v.x;
            Xs[kq*4+1][col] = v.y;
            Xs[kq*4+2][col] = v.z;
            Xs[kq*4+3][col] = v.w;
        }
        __syncthreads();
        #pragma unroll
        for (int kk = 0; kk < KC; kk++) {
            float2 w = *(const float2*)&Ws[kk][rt*2];
            unsigned long long w2v[2];
            w2v[0] = pack2f(w.x, w.x);
            w2v[1] = pack2f(w.y, w.y);
            const unsigned long long* xp = (const unsigned long long*)&Xs[kk][ct*8];
            unsigned long long x2v[4] = {xp[0], xp[1], xp[2], xp[3]};
            #pragma unroll
            for (int i = 0; i < 2; i++)
                #pragma unroll
                for (int j = 0; j < 4; j++) FMA_F32X2(acc2[i][j], w2v[i], x2v[j]);
        }
        __syncthreads();
    }
    #pragma unroll
    for (int i = 0; i < 2; i++) {
        int o = rt*2 + i;
        float vals[8];
        #pragma unroll
        for (int j = 0; j < 4; j++) {
            unsigned lo, hi;
            UNPACK_F32X2(lo, hi, acc2[i][j]);
            vals[2*j]   = __uint_as_float(lo);
            vals[2*j+1] = __uint_as_float(hi);
        }
        float* dst = out + (size_t)b*C2*NP + (size_t)o*NP + g0 + ct*8;
        #pragma unroll
        for (int j = 0; j < 8; j++)
            dst[j] = fmaxf(fmaf(ssc[o], vals[j], ssh[o]), 0.f);
    }
}

extern "C" void kernel_launch(void* const* d_in, const int* in_sizes, int n_in,
                              void* d_out, int out_size) {
    const float* p  = (const float*)d_in[0];
    const float* x  = (const float*)d_in[1];
    const float* Wt = (const float*)d_in[2];
    const float* gt = (const float*)d_in[3];
    const float* bt = (const float*)d_in[4];
    const float* mt = (const float*)d_in[5];
    const float* vt = (const float*)d_in[6];
    const float* Wc = (const float*)d_in[7];
    const float* gc = (const float*)d_in[8];
    const float* bc = (const float*)d_in[9];
    const float* mc = (const float*)d_in[10];
    const float* vc = (const float*)d_in[11];

    float* newp = (float*)d_out;                  // [8,1024,3]
    float* out  = (float*)d_out + BB*NP*3;        // [8,192,1024]

    // fused1 smem: FPS layout = 3*4096*4 + 4096*2 + 2*512*4 + 4096*2 + 64*4
    const int FUSED1_SMEM = 3*NN*4 + NN*2 + 2*512*4 + NN*2 + 64*4;  // 69888
    cudaFuncSetAttribute(fused1, cudaFuncAttributeMaxDynamicSharedMemorySize, FUSED1_SMEM);
    // fused2 smem: max(ballq 8*256*2=4096, gemmA 24576+8192+256+768=33792)
    const int FUSED2_SMEM = KC*C2*4 + KC*64*4 + 64*4 + C2*4;

    fused1<<<16 + BB*32, 512, FUSED1_SMEM>>>(p, x, Wt, gt, bt, mt, vt, newp);
    fused2<<<1024 + BB*16, 256, FUSED2_SMEM>>>(p, x, Wt, gt, vt);
    agg_kernel<<<(BB*NP)/4, 192>>>(p, newp);
    gemm2_kernel<<<(BB*NP)/16, 192>>>(Wc, gc, bc, mc, vc, out);
}

// round 11
// speedup vs baseline: 1.6292x; 1.0266x over previous
#include <cuda_runtime.h>
#include <math.h>
#include <stdint.h>

#define BB 8
#define NN 4096
#define CC 96
#define C2 192
#define NP 1024
#define NSAMP 16
#define FULLMASK 0xffffffffu
#define KC 32

// ---- packed f32x2 helpers (exact per-lane IEEE RN, sm_103a) ----
#define MUL_F32X2(out, a, b) \
    asm("mul.rn.f32x2 %0, %1, %2;" : "=l"(out) : "l"(a), "l"(b))
#define ADD_F32X2(out, a, b) \
    asm("add.rn.f32x2 %0, %1, %2;" : "=l"(out) : "l"(a), "l"(b))
#define FMA_F32X2(d, a, b) \
    asm("fma.rn.f32x2 %0, %1, %2, %0;" : "+l"(d) : "l"(a), "l"(b))
#define UNPACK_F32X2(lo, hi, in) \
    asm("mov.b64 {%0, %1}, %2;" : "=r"(lo), "=r"(hi) : "l"(in))

__device__ __forceinline__ unsigned long long pack2u(unsigned lo, unsigned hi) {
    unsigned long long r;
    asm("mov.b64 %0, {%1, %2};" : "=l"(r) : "r"(lo), "r"(hi));
    return r;
}
__device__ __forceinline__ unsigned long long pack2f(float lo, float hi) {
    return pack2u(__float_as_uint(lo), __float_as_uint(hi));
}

// ---------------- scratch ----------------
__device__ int   d_samp[BB*NP];
__device__ int   d_nbr[BB*NP*NSAMP];
__device__ float d_Bfeat[BB*NN*C2];    // [b][n][c]
__device__ float d_Afeat[BB*NP*C2];    // [b][g][c]
__device__ float d_Pool[BB*NP*C2];     // [b][g][c]
__device__ int   d_cellStart[BB][1001];
__device__ int   d_cellPts[BB][NN];

__device__ __forceinline__ int cellof(float x, float y, float z) {
    int ix = min(9, max(0, (int)(x * 9.99f)));
    int iy = min(9, max(0, (int)(y * 9.99f)));
    int iz = min(9, max(0, (int)(z * 9.99f)));
    return (ix * 10 + iy) * 10 + iz;
}

__device__ __forceinline__ int spread3(int b) {
    return (b & 1) | ((b & 2) << 2) | ((b & 4) << 4);
}

// ---------------- FPS body: 512 threads, 8 pts/thread, warp-bbox pruning ----------------
// Exactness: a warp skips ONLY when lb2(warp bbox)*0.999 >= warp_max(mind)
// (the prior iteration's stage-1 reduction value). Then every distance in the
// warp satisfies fl(d_i) >= lb2*0.999 >= mind_i (fp margin >100x rounding), so
// all minds are provably unchanged and cached (vmax, argpack) stay valid.
// Tie keys = origidx*4096+sortedpos => min original index (jnp.argmax order).
__device__ __forceinline__ void fps_body(char* smraw, const float* __restrict__ p,
                                         float* __restrict__ newp, int b) {
    float* ssx = (float*)smraw;                              // [4096] sorted coords
    float* ssy = ssx + NN;
    float* ssz = ssy + NN;
    unsigned short* sorig = (unsigned short*)(ssz + NN);     // [4096] orig index
    int* scnt  = (int*)(sorig + NN);                         // [512]
    int* scnt2 = scnt + 512;                                 // [512]
    unsigned short* scell = (unsigned short*)(scnt2 + 512);  // [4096]
    unsigned* sred = (unsigned*)(scell + NN);                // [64]

    int tid = threadIdx.x, lane = tid & 31, warp = tid >> 5;
    const float* pb = p + (size_t)b * NN * 3;

    // ---- counting sort into 512 Morton cells ----
    for (int i = tid; i < 512; i += 512) scnt[i] = 0;
    __syncthreads();
    for (int i = tid; i < NN; i += 512) {
        float xx = pb[3*i], yy = pb[3*i+1], zz = pb[3*i+2];
        int ix = min(7, max(0, (int)(xx * 8.0f)));
        int iy = min(7, max(0, (int)(yy * 8.0f)));
        int iz = min(7, max(0, (int)(zz * 8.0f)));
        int cell = (spread3(ix) << 2) | (spread3(iy) << 1) | spread3(iz);
        scell[i] = (unsigned short)cell;
        atomicAdd(&scnt[cell], 1);
    }
    __syncthreads();
    {
        int* src = scnt; int* dst = scnt2;
        for (int off = 1; off < 512; off <<= 1) {
            for (int i = tid; i < 512; i += 512)
                dst[i] = src[i] + ((i >= off) ? src[i - off] : 0);
            __syncthreads();
            int* t = src; src = dst; dst = t;
        }
        for (int i = tid; i < 512; i += 512)
            dst[i] = (i == 0) ? 0 : src[i-1];
        __syncthreads();
        for (int i = tid; i < NN; i += 512) {
            int cell = scell[i];
            int pos = atomicAdd(&dst[cell], 1);
            ssx[pos] = pb[3*i];
            ssy[pos] = pb[3*i+1];
            ssz[pos] = pb[3*i+2];
            sorig[pos] = (unsigned short)i;
        }
    }
    __syncthreads();

    // ---- my chunk: 8 sorted points ----
    const int base = tid * 8;
    float vx[8], vy[8], vz[8];
    #pragma unroll
    for (int i = 0; i < 8; i++) {
        vx[i] = ssx[base + i];
        vy[i] = ssy[base + i];
        vz[i] = ssz[base + i];
    }
    unsigned long long pxp[4], pyp[4], pzp[4];
    #pragma unroll
    for (int j = 0; j < 4; j++) {
        pxp[j] = pack2f(vx[2*j], vx[2*j+1]);
        pyp[j] = pack2f(vy[2*j], vy[2*j+1]);
        pzp[j] = pack2f(vz[2*j], vz[2*j+1]);
    }
    // lane bbox then warp bbox (union over lanes), one-time
    float bxlo = vx[0], bxhi = vx[0], bylo = vy[0], byhi = vy[0], bzlo = vz[0], bzhi = vz[0];
    #pragma unroll
    for (int i = 1; i < 8; i++) {
        bxlo = fminf(bxlo, vx[i]); bxhi = fmaxf(bxhi, vx[i]);
        bylo = fminf(bylo, vy[i]); byhi = fmaxf(byhi, vy[i]);
        bzlo = fminf(bzlo, vz[i]); bzhi = fmaxf(bzhi, vz[i]);
    }
    #pragma unroll
    for (int o = 16; o; o >>= 1) {
        bxlo = fminf(bxlo, __shfl_xor_sync(FULLMASK, bxlo, o));
        bxhi = fmaxf(bxhi, __shfl_xor_sync(FULLMASK, bxhi, o));
        bylo = fminf(bylo, __shfl_xor_sync(FULLMASK, bylo, o));
        byhi = fmaxf(byhi, __shfl_xor_sync(FULLMASK, byhi, o));
        bzlo = fminf(bzlo, __shfl_xor_sync(FULLMASK, bzlo, o));
        bzhi = fmaxf(bzhi, __shfl_xor_sync(FULLMASK, bzhi, o));
    }
    unsigned opack[8];
    #pragma unroll
    for (int i = 0; i < 8; i++)
        opack[i] = ((unsigned)sorig[base + i] << 12) | (unsigned)(base + i);

    float mind[8];
    #pragma unroll
    for (int i = 0; i < 8; i++) mind[i] = 1e10f;
    float vmaxf = 1e10f;
    unsigned apack = opack[0];
    unsigned wm = __float_as_uint(1e10f);     // warp max of mind (from prior reduction)

    float lx = pb[0], ly = pb[1], lz = pb[2];
    if (tid == 0) {
        d_samp[b*NP + 0] = 0;
        newp[(size_t)(b*NP)*3 + 0] = lx;
        newp[(size_t)(b*NP)*3 + 1] = ly;
        newp[(size_t)(b*NP)*3 + 2] = lz;
    }

    for (int k = 1; k < NP; k++) {
        // uniform warp-bbox test against warp's current mind-max (wm)
        float tx = fmaxf(fmaxf(bxlo - lx, lx - bxhi), 0.f);
        float ty = fmaxf(fmaxf(bylo - ly, ly - byhi), 0.f);
        float tz = fmaxf(fmaxf(bzlo - lz, lz - bzhi), 0.f);
        float lb2 = tx*tx + ty*ty + tz*tz;
        if (lb2 * 0.999f < __uint_as_float(wm)) {
            unsigned long long nlx = pack2f(-lx, -lx);
            unsigned long long nly = pack2f(-ly, -ly);
            unsigned long long nlz = pack2f(-lz, -lz);
            #pragma unroll
            for (int j = 0; j < 4; j++) {
                unsigned long long dx, dy, dz, t1, t2, t3, s;
                ADD_F32X2(dx, pxp[j], nlx);
                ADD_F32X2(dy, pyp[j], nly);
                ADD_F32X2(dz, pzp[j], nlz);
                MUL_F32X2(t1, dx, dx);
                MUL_F32X2(t2, dy, dy);
                MUL_F32X2(t3, dz, dz);
                ADD_F32X2(s, t1, t2);
                ADD_F32X2(s, s, t3);
                unsigned lo, hi;
                UNPACK_F32X2(lo, hi, s);
                mind[2*j]   = fminf(mind[2*j],   __uint_as_float(lo));
                mind[2*j+1] = fminf(mind[2*j+1], __uint_as_float(hi));
            }
            float a0 = fmaxf(mind[0], mind[1]), a1 = fmaxf(mind[2], mind[3]);
            float a2 = fmaxf(mind[4], mind[5]), a3 = fmaxf(mind[6], mind[7]);
            float v = fmaxf(fmaxf(a0, a1), fmaxf(a2, a3));
            unsigned ci[8];
            #pragma unroll
            for (int i = 0; i < 8; i++)
                ci[i] = (mind[i] == v) ? opack[i] : 0xffffffffu;
            #pragma unroll
            for (int s2 = 4; s2; s2 >>= 1)
                #pragma unroll
                for (int i = 0; i < 4; i++)
                    if (i < s2) ci[i] = min(ci[i], ci[i + s2]);
            vmaxf = v;
            apack = ci[0];
        }
        // warp reduce (dist >= 0 so uint order on bits == float order)
        unsigned vb = __float_as_uint(vmaxf);
        unsigned m = __reduce_max_sync(FULLMASK, vb);
        unsigned cand = (vb == m) ? apack : 0xffffffffu;
        unsigned l = __reduce_min_sync(FULLMASK, cand);
        wm = m;

        int par = (k & 1) << 4;
        if (lane == 0) { sred[par + warp] = m; sred[32 + par + warp] = l; }
        __syncthreads();
        unsigned v16 = (lane < 16) ? sred[par + lane] : 0u;
        unsigned bm = __reduce_max_sync(FULLMASK, v16);
        unsigned i16 = (lane < 16 && v16 == bm) ? sred[32 + par + lane] : 0xffffffffu;
        unsigned wp = __reduce_min_sync(FULLMASK, i16);

        int spos = (int)(wp & 4095u);
        lx = ssx[spos]; ly = ssy[spos]; lz = ssz[spos];
        if (tid == 0) {
            d_samp[b*NP + k] = (int)(wp >> 12);
            newp[(size_t)(b*NP + k)*3 + 0] = lx;
            newp[(size_t)(b*NP + k)*3 + 1] = ly;
            newp[(size_t)(b*NP + k)*3 + 2] = lz;
        }
    }
}

// ---------------- grid build body: 512 threads, 1 block per batch ----------------
__device__ __forceinline__ void gridbuild_body(char* smraw, const float* __restrict__ p, int b) {
    int* a  = (int*)smraw;        // 1024
    int* bb = a + 1024;           // 1024
    int tid = threadIdx.x;
    const float* pb = p + (size_t)b * NN * 3;

    for (int i = tid; i < 1024; i += 512) a[i] = 0;
    __syncthreads();

    int mycell[8];
    #pragma unroll
    for (int e = 0; e < 8; e++) {
        int i = e*512 + tid;
        int c = cellof(pb[3*i], pb[3*i+1], pb[3*i+2]);
        mycell[e] = c;
        atomicAdd(&a[c], 1);
    }
    __syncthreads();

    int* src = a; int* dst = bb;
    for (int off = 1; off < 1024; off <<= 1) {
        for (int i = tid; i < 1024; i += 512)
            dst[i] = src[i] + ((i >= off) ? src[i - off] : 0);
        __syncthreads();
        int* t = src; src = dst; dst = t;
    }
    for (int i = tid; i <= 1000; i += 512)
        d_cellStart[b][i] = (i == 0) ? 0 : src[i-1];
    for (int i = tid; i < 1000; i += 512)
        dst[i] = (i == 0) ? 0 : src[i-1];       // cursors
    __syncthreads();

    #pragma unroll
    for (int e = 0; e < 8; e++) {
        int i = e*512 + tid;
        int slot = atomicAdd(&dst[mycell[e]], 1);
        d_cellPts[b][slot] = i;
    }
}

// ---------------- gemmB body: 512 thr, tile 192x128, thread tile 6x8 ----------------
__device__ __forceinline__ void gemmB_body(char* smraw, const float* __restrict__ x,
                                           const float* __restrict__ Wt,
                                           const float* __restrict__ gt, const float* __restrict__ bt,
                                           const float* __restrict__ mt, const float* __restrict__ vt,
                                           int rb) {
    float (*Ws)[C2]  = (float (*)[C2])smraw;                      // [32][192]
    float (*Xs)[128] = (float (*)[128])(smraw + KC*C2*4);         // [32][128]
    float* ssc = (float*)(smraw + KC*C2*4 + KC*128*4);            // [192]
    float* ssh = ssc + C2;

    int tid = threadIdx.x;
    int b = rb >> 5, n0 = (rb & 31) * 128;
    if (tid < C2) {
        float st = gt[tid] / sqrtf(vt[tid] + 1e-5f);
        ssc[tid] = st;
        ssh[tid] = bt[tid] - mt[tid]*st;
    }
    int rt = tid >> 4, ct = tid & 15;      // rows rt*6.., cols ct*8..
    float acc[6][8];
    #pragma unroll
    for (int i = 0; i < 6; i++)
        #pragma unroll
        for (int j = 0; j < 8; j++) acc[i][j] = 0.f;

    for (int kc = 0; kc < CC; kc += KC) {
        if (tid < C2) {
            const float4* wr = (const float4*)(Wt + (size_t)tid*C2 + CC + kc);
            #pragma unroll
            for (int q = 0; q < 8; q++) {
                float4 w = wr[q];
                Ws[q*4+0][tid] = w.x; Ws[q*4+1][tid] = w.y;
                Ws[q*4+2][tid] = w.z; Ws[q*4+3][tid] = w.w;
            }
        }
        #pragma unroll
        for (int e = 0; e < 8; e++) {
            int idx = e*512 + tid;
            int kk = idx >> 7, nn = idx & 127;
            Xs[kk][nn] = fmaxf(x[((size_t)b*CC + kc + kk)*NN + n0 + nn], 0.f);
        }
        __syncthreads();
        #pragma unroll
        for (int kk = 0; kk < KC; kk++) {
            float wf[6], xf[8];
            const float2* wp = (const float2*)&Ws[kk][rt*6];
            float2 w0 = wp[0], w1 = wp[1], w2 = wp[2];
            wf[0]=w0.x; wf[1]=w0.y; wf[2]=w1.x; wf[3]=w1.y; wf[4]=w2.x; wf[5]=w2.y;
            const float4* xp = (const float4*)&Xs[kk][ct*8];
            float4 x0 = xp[0], x1 = xp[1];
            xf[0]=x0.x; xf[1]=x0.y; xf[2]=x0.z; xf[3]=x0.w;
            xf[4]=x1.x; xf[5]=x1.y; xf[6]=x1.z; xf[7]=x1.w;
            #pragma unroll
            for (int i = 0; i < 6; i++)
                #pragma unroll
                for (int j = 0; j < 8; j++) acc[i][j] = fmaf(wf[i], xf[j], acc[i][j]);
        }
        __syncthreads();
    }
    #pragma unroll
    for (int j = 0; j < 8; j++) {
        int n = n0 + ct*8 + j;
        float* dst = d_Bfeat + ((size_t)(b*NN + n))*C2 + rt*6;
        #pragma unroll
        for (int i = 0; i < 6; i++)
            dst[i] = fmaf(ssc[rt*6+i], acc[i][j], ssh[rt*6+i]);
    }
}

// ---------------- fused1: blocks 0-7 FPS, 8-15 grid build, 16-271 gemmB ----------------
__global__ __launch_bounds__(512, 1) void fused1(const float* __restrict__ p,
                                                 const float* __restrict__ x,
                                                 const float* __restrict__ Wt,
                                                 const float* __restrict__ gt,
                                                 const float* __restrict__ bt,
                                                 const float* __restrict__ mt,
                                                 const float* __restrict__ vt,
                                                 float* __restrict__ newp) {
    extern __shared__ char sm[];
    int bid = blockIdx.x;
    if (bid < 8)       fps_body(sm, p, newp, bid);
    else if (bid < 16) gridbuild_body(sm, p, bid - 8);
    else               gemmB_body(sm, x, Wt, gt, bt, mt, vt, bid - 16);
}

// ---------------- ball query body: 8 warps/block, 1 warp per center ----------------
__device__ __forceinline__ void ballq_body(char* smraw, const float* __restrict__ p, int bid) {
    unsigned short (*lists)[256] = (unsigned short (*)[256])smraw;
    int warp = threadIdx.x >> 5, lane = threadIdx.x & 31;
    int gc = bid * 8 + warp;       // b*1024 + g
    int b = gc >> 10;
    int cIdx = d_samp[gc];
    const float* pb = p + (size_t)b * NN * 3;
    float cx = pb[3*cIdx], cy = pb[3*cIdx+1], cz = pb[3*cIdx+2];
    int ccx = min(9, max(0, (int)(cx * 9.99f)));
    int ccy = min(9, max(0, (int)(cy * 9.99f)));
    int ccz = min(9, max(0, (int)(cz * 9.99f)));
    const float R2 = (float)(0.1 * 0.1);
    unsigned short* lst = lists[warp];
    const int* cs = d_cellStart[b];
    int hcnt = 0;

    int ix1 = min(9, ccx+1), iy1 = min(9, ccy+1), iz1 = min(9, ccz+1);
    for (int ix = max(0, ccx-1); ix <= ix1; ix++)
    for (int iy = max(0, ccy-1); iy <= iy1; iy++)
    for (int iz = max(0, ccz-1); iz <= iz1; iz++) {
        int cell = (ix*10 + iy)*10 + iz;
        int s = cs[cell], e = cs[cell + 1];
        for (int ob = s; ob < e; ob += 32) {
            int o = ob + lane;
            bool valid = o < e;
            int pid = valid ? d_cellPts[b][o] : 0;
            float dx = __fsub_rn(cx, pb[3*pid+0]);
            float dy = __fsub_rn(cy, pb[3*pid+1]);
            float dz = __fsub_rn(cz, pb[3*pid+2]);
            float d2 = __fadd_rn(__fadd_rn(__fmul_rn(dx,dx), __fmul_rn(dy,dy)), __fmul_rn(dz,dz));
            bool hit = valid && (d2 < R2);
            unsigned mb = __ballot_sync(FULLMASK, hit);
            if (hit) {
                int ps = hcnt + __popc(mb & ((1u << lane) - 1u));
                if (ps < 256) lst[ps] = (unsigned short)pid;
            }
            hcnt += __popc(mb);
        }
    }
    __syncwarp();
    int hs = min(hcnt, 256);
    int* outp = d_nbr + (size_t)gc * NSAMP;
    if (hs <= 32) {
        unsigned rv = (lane < hs) ? (unsigned)lst[lane] : 0xffffffffu;
        unsigned first = 0;
        #pragma unroll
        for (int r = 0; r < NSAMP; r++) {
            unsigned best = __reduce_min_sync(FULLMASK, rv);
            if (r == 0) first = best;
            if (lane == r) outp[r] = (int)((r < hs) ? best : first);
            if (rv == best) rv = 0xffffffffu;
        }
    } else {
        for (int r = 0; r < NSAMP; r++) {
            unsigned lm = 0xffffffffu;
            for (int j = lane; j < hs; j += 32) lm = min(lm, (unsigned)lst[j]);
            unsigned best = __reduce_min_sync(FULLMASK, lm);
            if (lane == r) outp[r] = (int)best;
            for (int j = lane; j < hs; j += 32) if (lst[j] == best) lst[j] = 0xffff;
            __syncwarp();
        }
    }
}

// ---------------- gemmA body: 256 thr, tile 192x64, 6x8/thread, f32x2 ----------------
__device__ __forceinline__ void gemmA_body(char* smraw, const float* __restrict__ x,
                                           const float* __restrict__ Wt,
                                           const float* __restrict__ gt,
                                           const float* __restrict__ vt, int rb) {
    float (*Ws)[C2] = (float (*)[C2])smraw;                  // [32][192]
    float (*Xs)[64] = (float (*)[64])(smraw + KC*C2*4);      // [32][64]
    int*   sidx = (int*)(smraw + KC*C2*4 + KC*64*4);         // [64]
    float* ssc  = (float*)(sidx + 64);                       // [192]

    int b  = rb >> 4;
    int g0 = (rb & 15) * 64;
    int tid = threadIdx.x;
    int rt = tid >> 3, ct = tid & 7;
    if (tid < 64) sidx[tid] = d_samp[b*NP + g0 + tid];
    if (tid < C2) ssc[tid] = gt[tid] / sqrtf(vt[tid] + 1e-5f);
    unsigned long long acc2[6][4];
    #pragma unroll
    for (int i = 0; i < 6; i++)
        #pragma unroll
        for (int j = 0; j < 4; j++) acc2[i][j] = 0ull;

    for (int kc = 0; kc < CC; kc += KC) {
        if (tid < C2) {
            const float4* wr = (const float4*)(Wt + (size_t)tid*C2 + kc);
            #pragma unroll
            for (int q = 0; q < 8; q++) {
                float4 w = wr[q];
                Ws[q*4+0][tid] = w.x; Ws[q*4+1][tid] = w.y;
                Ws[q*4+2][tid] = w.z; Ws[q*4+3][tid] = w.w;
            }
        }
        __syncthreads();
        #pragma unroll
        for (int e = 0; e < 8; e++) {
            int idx = e*256 + tid;
            int kk = idx >> 6, nn = idx & 63;
            Xs[kk][nn] = fmaxf(x[((size_t)b*CC + kc + kk)*NN + sidx[nn]], 0.f);
        }
        __syncthreads();
        #pragma unroll
        for (int kk = 0; kk < KC; kk++) {
            const float2* wp = (const float2*)&Ws[kk][rt*6];
            float2 w0 = wp[0], w1 = wp[1], w2 = wp[2];
            unsigned long long w2v[6];
            w2v[0] = pack2f(w0.x, w0.x); w2v[1] = pack2f(w0.y, w0.y);
            w2v[2] = pack2f(w1.x, w1.x); w2v[3] = pack2f(w1.y, w1.y);
            w2v[4] = pack2f(w2.x, w2.x); w2v[5] = pack2f(w2.y, w2.y);
            const unsigned long long* xp = (const unsigned long long*)&Xs[kk][ct*8];
            unsigned long long x2v[4] = {xp[0], xp[1], xp[2], xp[3]};
            #pragma unroll
            for (int i = 0; i < 6; i++)
                #pragma unroll
                for (int j = 0; j < 4; j++) FMA_F32X2(acc2[i][j], w2v[i], x2v[j]);
        }
        __syncthreads();
    }
    float acc[6][8];
    #pragma unroll
    for (int i = 0; i < 6; i++)
        #pragma unroll
        for (int j = 0; j < 4; j++) {
            unsigned lo, hi;
            UNPACK_F32X2(lo, hi, acc2[i][j]);
            acc[i][2*j] = __uint_as_float(lo);
            acc[i][2*j+1] = __uint_as_float(hi);
        }
    #pragma unroll
    for (int j = 0; j < 8; j++) {
        int g = g0 + ct*8 + j;
        float* dst = d_Afeat + ((size_t)(b*NP + g))*C2 + rt*6;
        #pragma unroll
        for (int i = 0; i < 6; i++) dst[i] = ssc[rt*6+i] * acc[i][j];
    }
}

// ---------------- fused2: blocks 0-1023 ballq, 1024-1151 gemmA ----------------
__global__ __launch_bounds__(256) void fused2(const float* __restrict__ p,
                                              const float* __restrict__ x,
                                              const float* __restrict__ Wt,
                                              const float* __restrict__ gt,
                                              const float* __restrict__ vt) {
    extern __shared__ char sm[];
    int bid = blockIdx.x;
    if (bid < 1024) ballq_body(sm, p, bid);
    else            gemmA_body(sm, x, Wt, gt, vt, bid - 1024);
}

// ---------------- aggregation: 4 centers/block, float4 channels ----------------
__global__ __launch_bounds__(192) void agg_kernel(const float* __restrict__ p,
                                                  const float* __restrict__ newp) {
    int bg0 = blockIdx.x * 4;
    int b   = bg0 >> 10;
    int tid = threadIdx.x;
    __shared__ int   snbr[4][16];
    __shared__ float sctr[4][3];
    __shared__ float sp[4][16][3];
    if (tid < 64) snbr[tid >> 4][tid & 15] = d_nbr[(size_t)bg0*NSAMP + tid];
    if (tid < 12) sctr[tid / 3][tid % 3] = newp[(size_t)bg0*3 + tid];
    __syncthreads();
    {
        int ci = tid / 48, rem = tid % 48, s = rem / 3, d = rem % 3;
        sp[ci][s][d] = p[((size_t)(b*NN + snbr[ci][s]))*3 + d];
    }
    __syncthreads();

    int ci = tid / 48, t = tid % 48;
    int ch0 = t * 4;
    int bg  = bg0 + ci;
    int dim = ch0 >> 6;
    int r0  = ch0 & 63;
    bool isSin = r0 < 32;
    int j0 = isSin ? r0 : (r0 - 32);
    float pm[4];
    #pragma unroll
    for (int q = 0; q < 4; q++)
        pm[q] = 50.0f * exp2f(-(float)(j0 + q) * (8.965784284662087f / 32.0f));
    float ctr = sctr[ci][dim];
    float4 a4 = *(const float4*)&d_Afeat[(size_t)bg*C2 + ch0];

    int   ni[16];
    float dpd[16];
    #pragma unroll
    for (int s = 0; s < NSAMP; s++) {
        ni[s]  = snbr[ci][s];
        dpd[s] = sp[ci][s][dim] - ctr;
    }

    float vmax[4], vsum[4];
    #pragma unroll
    for (int q = 0; q < 4; q++) { vmax[q] = -INFINITY; vsum[q] = 0.f; }

    #pragma unroll 4
    for (int s = 0; s < NSAMP; s++) {
        float4 bv = *(const float4*)&d_Bfeat[((size_t)(b*NN + ni[s]))*C2 + ch0];
        float tq[4];
        tq[0] = fmaxf(a4.x + bv.x, 0.f);
        tq[1] = fmaxf(a4.y + bv.y, 0.f);
        tq[2] = fmaxf(a4.z + bv.z, 0.f);
        tq[3] = fmaxf(a4.w + bv.w, 0.f);
        #pragma unroll
        for (int q = 0; q < 4; q++) {
            float pos = dpd[s] * pm[q];
            float e = isSin ? __sinf(pos) : __cosf(pos);
            float ag = fmaf(tq[q], e, e);
            vmax[q] = fmaxf(vmax[q], ag);
            vsum[q] += ag;
        }
    }
    float4 outv;
    outv.x = fmaxf(vmax[0] + vsum[0]*(1.0f/16.0f), 0.f);
    outv.y = fmaxf(vmax[1] + vsum[1]*(1.0f/16.0f), 0.f);
    outv.z = fmaxf(vmax[2] + vsum[2]*(1.0f/16.0f), 0.f);
    outv.w = fmaxf(vmax[3] + vsum[3]*(1.0f/16.0f), 0.f);
    *(float4*)&d_Pool[(size_t)bg*C2 + ch0] = outv;
}

// ---------------- final conv: 128 blocks, 192x64 tiles, 8x8/thread, f32x2 ----------------
__global__ __launch_bounds__(192) void gemm2_kernel(const float* __restrict__ Wc,
                                                    const float* __restrict__ gc,
                                                    const float* __restrict__ bc,
                                                    const float* __restrict__ mc,
                                                    const float* __restrict__ vc,
                                                    float* __restrict__ out) {
    __shared__ __align__(16) float Ws[KC][C2];
    __shared__ __align__(16) float Xs[KC][64];
    __shared__ float ssc[C2], ssh[C2];
    int col0 = blockIdx.x * 64;
    int b  = col0 >> 10;
    int g0 = col0 & 1023;
    int tid = threadIdx.x;
    int rt = tid >> 3, ct = tid & 7;     // rows rt*8.., cols ct*8..
    {
        float st = gc[tid] / sqrtf(vc[tid] + 1e-5f);
        ssc[tid] = st;
        ssh[tid] = bc[tid] - mc[tid]*st;
    }
    unsigned long long acc2[8][4];
    #pragma unroll
    for (int i = 0; i < 8; i++)
        #pragma unroll
        for (int j = 0; j < 4; j++) acc2[i][j] = 0ull;

    for (int kc = 0; kc < C2; kc += KC) {
        {
            const float4* wr = (const float4*)(Wc + (size_t)tid*C2 + kc);
            #pragma unroll
            for (int q = 0; q < 8; q++) {
                float4 w = wr[q];
                Ws[q*4+0][tid] = w.x; Ws[q*4+1][tid] = w.y;
                Ws[q*4+2][tid] = w.z; Ws[q*4+3][tid] = w.w;
            }
        }
        if (tid < 64) {
            const float4* src = (const float4*)(d_Pool + (size_t)(col0 + tid)*C2 + kc);
            #pragma unroll
            for (int q = 0; q < KC/4; q++) {
                float4 v = src[q];
                Xs[q*4+0][tid] = v.x;
                Xs[q*4+1][tid] = v.y;
                Xs[q*4+2][tid] = v.z;
                Xs[q*4+3][tid] = v.w;
            }
        }
        __syncthreads();
        #pragma unroll
        for (int kk = 0; kk < KC; kk++) {
            const float4* wp = (const float4*)&Ws[kk][rt*8];
            float4 wa = wp[0], wb = wp[1];
            unsigned long long w2v[8];
            w2v[0] = pack2f(wa.x, wa.x); w2v[1] = pack2f(wa.y, wa.y);
            w2v[2] = pack2f(wa.z, wa.z); w2v[3] = pack2f(wa.w, wa.w);
            w2v[4] = pack2f(wb.x, wb.x); w2v[5] = pack2f(wb.y, wb.y);
            w2v[6] = pack2f(wb.z, wb.z); w2v[7] = pack2f(wb.w, wb.w);
            const unsigned long long* xp = (const unsigned long long*)&Xs[kk][ct*8];
            unsigned long long x2v[4] = {xp[0], xp[1], xp[2], xp[3]};
            #pragma unroll
            for (int i = 0; i < 8; i++)
                #pragma unroll
                for (int j = 0; j < 4; j++) FMA_F32X2(acc2[i][j], w2v[i], x2v[j]);
        }
        __syncthreads();
    }
    #pragma unroll
    for (int i = 0; i < 8; i++) {
        int o = rt*8 + i;
        float vals[8];
        #pragma unroll
        for (int j = 0; j < 4; j++) {
            unsigned lo, hi;
            UNPACK_F32X2(lo, hi, acc2[i][j]);
            vals[2*j]   = __uint_as_float(lo);
            vals[2*j+1] = __uint_as_float(hi);
        }
        float* dst = out + (size_t)b*C2*NP + (size_t)o*NP + g0 + ct*8;
        #pragma unroll
        for (int j = 0; j < 8; j++)
            dst[j] = fmaxf(fmaf(ssc[o], vals[j], ssh[o]), 0.f);
    }
}

extern "C" void kernel_launch(void* const* d_in, const int* in_sizes, int n_in,
                              void* d_out, int out_size) {
    const float* p  = (const float*)d_in[0];
    const float* x  = (const float*)d_in[1];
    const float* Wt = (const float*)d_in[2];
    const float* gt = (const float*)d_in[3];
    const float* bt = (const float*)d_in[4];
    const float* mt = (const float*)d_in[5];
    const float* vt = (const float*)d_in[6];
    const float* Wc = (const float*)d_in[7];
    const float* gc = (const float*)d_in[8];
    const float* bc = (const float*)d_in[9];
    const float* mc = (const float*)d_in[10];
    const float* vc = (const float*)d_in[11];

    float* newp = (float*)d_out;                  // [8,1024,3]
    float* out  = (float*)d_out + BB*NP*3;        // [8,192,1024]

    // fused1 smem: FPS layout = 3*4096*4 + 4096*2 + 2*512*4 + 4096*2 + 64*4
    const int FUSED1_SMEM = 3*NN*4 + NN*2 + 2*512*4 + NN*2 + 64*4;  // 69888
    cudaFuncSetAttribute(fused1, cudaFuncAttributeMaxDynamicSharedMemorySize, FUSED1_SMEM);
    // fused2 smem: max(ballq 8*256*2=4096, gemmA 24576+8192+256+768=33792)
    const int FUSED2_SMEM = KC*C2*4 + KC*64*4 + 64*4 + C2*4;

    fused1<<<16 + BB*32, 512, FUSED1_SMEM>>>(p, x, Wt, gt, bt, mt, vt, newp);
    fused2<<<1024 + BB*16, 256, FUSED2_SMEM>>>(p, x, Wt, gt, vt);
    agg_kernel<<<(BB*NP)/4, 192>>>(p, newp);
    gemm2_kernel<<<(BB*NP)/64, 192>>>(Wc, gc, bc, mc, vc, out);
}